// round 6
// baseline (speedup 1.0000x reference)
#include <cuda_runtime.h>
#include <cuda_fp16.h>
#include <cuda_bf16.h>
#include <cstdint>

#define OUT_F 11008
#define IN_F  4096
#define NGROW 32            // groups per output row (4096/128)
#define LUT_N (352256 * 16)
#define TPB   512
#define WPB   16            // warps per block

// Permuted transposed x: slot = (g*4 + j)*32 + lane holds column c = g*128 + 4*lane + j
__device__ float4 g_xa[IN_F];   // batches 0-3
__device__ float4 g_xb[IN_F];   // batches 4-7

__global__ void transpose_x_kernel(const float* __restrict__ x) {
    int c = blockIdx.x * blockDim.x + threadIdx.x;
    if (c < IN_F) {
        int g = c >> 7, w = c & 127, l = w >> 2, j = w & 3;
        int slot = (g * 4 + j) * 32 + l;
        float4 a, b;
        a.x = x[0 * IN_F + c]; a.y = x[1 * IN_F + c];
        a.z = x[2 * IN_F + c]; a.w = x[3 * IN_F + c];
        b.x = x[4 * IN_F + c]; b.y = x[5 * IN_F + c];
        b.z = x[6 * IN_F + c]; b.w = x[7 * IN_F + c];
        g_xa[slot] = a; g_xb[slot] = b;
    }
}

__device__ __forceinline__ bool plaus(float v) {
    float a = fabsf(v);
    return isfinite(v) && a > 1e-4f && a < 0.25f;
}

__device__ __forceinline__ float cvtE(__half v)        { return __half2float(v); }
__device__ __forceinline__ float cvtE(__nv_bfloat16 v) { return __bfloat162float(v); }
__device__ __forceinline__ float cvtE(float v)         { return v; }

__device__ __forceinline__ unsigned long long dup2(float w) {
    unsigned long long r;
    asm("mov.b64 %0, {%1, %1};" : "=l"(r) : "f"(w));
    return r;
}
__device__ __forceinline__ void ffma2(unsigned long long& d,
                                      unsigned long long a,
                                      unsigned long long b) {
    asm("fma.rn.f32x2 %0, %1, %2, %0;" : "+l"(d) : "l"(a), "l"(b));
}

template <int U, typename E>
__device__ __forceinline__ void row_pass(
    const int* __restrict__ widx,
    const E* __restrict__ lut,
    const float* __restrict__ bias,
    float* __restrict__ out,
    int rs, int lane)
{
    constexpr int NP = (U + 1) / 2;   // LUT row-pairs held in registers

    const ulonglong2* __restrict__ xa = reinterpret_cast<const ulonglong2*>(g_xa);
    const ulonglong2* __restrict__ xb = reinterpret_cast<const ulonglong2*>(g_xb);

    const int4* wbase = reinterpret_cast<const int4*>(widx) + (size_t)rs * (IN_F / 4) + lane;
    const E*    lbase = lut + (size_t)rs * (NGROW * 16);

    const int uprime = lane >> 4;     // which row of the pair this lane serves
    const int eidx   = lane & 15;     // which palette entry this lane holds

    unsigned long long acc[U][4];
#pragma unroll
    for (int u = 0; u < U; u++)
#pragma unroll
        for (int j = 0; j < 4; j++) acc[u][j] = 0ull;

    // ---- prologue: prefetch idx + LUT rows for group 0 ----
    int4 nxt[U];
#pragma unroll
    for (int u = 0; u < U; u++)
        nxt[u] = __ldcs(wbase + u * (IN_F / 4));

    float lv[NP];
#pragma unroll
    for (int p = 0; p < NP; p++) {
        int u = 2 * p + uprime;
        lv[p] = (u < U) ? cvtE(__ldcs(lbase + (size_t)u * (NGROW * 16) + eidx)) : 0.0f;
    }

    for (int g = 0; g < NGROW; g++) {
        int4 cur[U];
#pragma unroll
        for (int u = 0; u < U; u++) cur[u] = nxt[u];
        float lvc[NP];
#pragma unroll
        for (int p = 0; p < NP; p++) lvc[p] = lv[p];

        // prefetch next group's idx + LUT rows (addresses independent of data)
        if (g + 1 < NGROW) {
#pragma unroll
            for (int u = 0; u < U; u++)
                nxt[u] = __ldcs(wbase + u * (IN_F / 4) + (g + 1) * 32);
#pragma unroll
            for (int p = 0; p < NP; p++) {
                int u = 2 * p + uprime;
                lv[p] = (u < U) ? cvtE(__ldcs(lbase + (size_t)u * (NGROW * 16)
                                              + (g + 1) * 16 + eidx)) : 0.0f;
            }
        }

#pragma unroll
        for (int j = 0; j < 4; j++) {
            int xoff = (g * 4 + j) * 32 + lane;
            ulonglong2 va = __ldg(&xa[xoff]);   // L1-resident, coalesced
            ulonglong2 vb = __ldg(&xb[xoff]);
#pragma unroll
            for (int u = 0; u < U; u++) {
                int id = reinterpret_cast<const int*>(&cur[u])[j];
                // register-gather: LUT value lives in lane ((u&1)*16 + id) of lvc[u/2]
                float w = __shfl_sync(0xffffffffu, lvc[u >> 1], ((u & 1) << 4) | id, 32);
                unsigned long long w2 = dup2(w);
                ffma2(acc[u][0], w2, va.x);
                ffma2(acc[u][1], w2, va.y);
                ffma2(acc[u][2], w2, vb.x);
                ffma2(acc[u][3], w2, vb.y);
            }
        }
    }

    // unpack and warp-reduce
    float accf[U][8];
#pragma unroll
    for (int u = 0; u < U; u++)
#pragma unroll
        for (int j = 0; j < 4; j++) {
            unsigned int lo, hi;
            asm("mov.b64 {%0, %1}, %2;" : "=r"(lo), "=r"(hi) : "l"(acc[u][j]));
            accf[u][2 * j]     = __uint_as_float(lo);
            accf[u][2 * j + 1] = __uint_as_float(hi);
        }

#pragma unroll
    for (int off = 16; off > 0; off >>= 1)
#pragma unroll
        for (int u = 0; u < U; u++)
#pragma unroll
            for (int b = 0; b < 8; b++)
                accf[u][b] += __shfl_xor_sync(0xffffffffu, accf[u][b], off);

    if (lane == 0) {
#pragma unroll
        for (int u = 0; u < U; u++) {
            float bv = bias[rs + u];
#pragma unroll
            for (int b = 0; b < 8; b++)
                out[(size_t)b * OUT_F + rs + u] = accf[u][b] + bv;
        }
    }
}

template <typename E>
__device__ __forceinline__ void dispatch_rows(
    const int* __restrict__ widx, const E* __restrict__ lut,
    const float* __restrict__ bias, float* __restrict__ out,
    int rs, int nr, int lane)
{
    switch (nr) {
        case 4: row_pass<4, E>(widx, lut, bias, out, rs, lane); break;
        case 5: row_pass<5, E>(widx, lut, bias, out, rs, lane); break;
        case 3: row_pass<3, E>(widx, lut, bias, out, rs, lane); break;
        case 2: row_pass<2, E>(widx, lut, bias, out, rs, lane); break;
        case 1: row_pass<1, E>(widx, lut, bias, out, rs, lane); break;
        default: {
            int r = rs;
            for (; r + 4 <= rs + nr; r += 4) row_pass<4, E>(widx, lut, bias, out, r, lane);
            for (; r < rs + nr; r++)         row_pass<1, E>(widx, lut, bias, out, r, lane);
            break;
        }
    }
}

__global__ void __launch_bounds__(TPB, 1) pallet_kernel(
    const int* __restrict__ widx,
    const void* __restrict__ lut,
    const float* __restrict__ bias,
    float* __restrict__ out,
    int nwarps)
{
    __shared__ int s_mode;
    int tid = threadIdx.x, warp = tid >> 5, lane = tid & 31;

    // inline dtype probe (warp 0, 64 samples): how was the fp16 LUT materialized?
    if (warp == 0) {
        const unsigned short* s = (const unsigned short*)lut;
        const float* f = (const float*)lut;
        int ch = 0, cb = 0, cf = 0;
        for (int t = lane; t < 64; t += 32) {
            unsigned short v = s[t];
            if (plaus(__half2float(__ushort_as_half(v)))) ch++;
            if (plaus(__uint_as_float(((unsigned)v) << 16))) cb++;   // bf16 -> f32
            if (plaus(f[t])) cf++;
        }
#pragma unroll
        for (int o = 16; o > 0; o >>= 1) {
            ch += __shfl_xor_sync(0xffffffffu, ch, o);
            cb += __shfl_xor_sync(0xffffffffu, cb, o);
            cf += __shfl_xor_sync(0xffffffffu, cf, o);
        }
        if (lane == 0) {
            int m = 0, best = ch;
            if (cb > best) { best = cb; m = 1; }
            if (cf > best) { best = cf; m = 2; }
            s_mode = m;
        }
    }
    __syncthreads();
    int mode = s_mode;

    int w = blockIdx.x * WPB + warp;
    long long s = ((long long)w * OUT_F) / nwarps;
    long long e = ((long long)(w + 1) * OUT_F) / nwarps;
    int rs = (int)s;
    int nr = (int)(e - s);

    if (mode == 0)
        dispatch_rows<__half>(widx, (const __half*)lut, bias, out, rs, nr, lane);
    else if (mode == 1)
        dispatch_rows<__nv_bfloat16>(widx, (const __nv_bfloat16*)lut, bias, out, rs, nr, lane);
    else
        dispatch_rows<float>(widx, (const float*)lut, bias, out, rs, nr, lane);
}

extern "C" void kernel_launch(void* const* d_in, const int* in_sizes, int n_in,
                              void* d_out, int out_size) {
    // Bind inputs by element count (all four distinct):
    //   x: 32768, weight_indices: 45088768, lut: 5636096, bias: 11008
    const float* x    = nullptr;
    const int*   widx = nullptr;
    const void*  lut  = nullptr;
    const float* bias = nullptr;

    for (int i = 0; i < n_in; i++) {
        long long n = in_sizes[i];
        if (n == 8LL * IN_F)                   x    = (const float*)d_in[i];
        else if (n == (long long)OUT_F * IN_F) widx = (const int*)d_in[i];
        else if (n == (long long)LUT_N)        lut  = d_in[i];
        else if (n == OUT_F)                   bias = (const float*)d_in[i];
    }
    if (!x || !widx || !lut || !bias) {
        x    = (const float*)d_in[0];
        widx = (const int*)d_in[1];
        lut  = d_in[2];
        bias = (const float*)d_in[3];
    }

    float* out = (float*)d_out;

    int dev = 0, sms = 148;
    cudaGetDevice(&dev);
    cudaDeviceGetAttribute(&sms, cudaDevAttrMultiProcessorCount, dev);

    transpose_x_kernel<<<(IN_F + 255) / 256, 256>>>(x);
    pallet_kernel<<<sms, TPB>>>(widx, lut, bias, out, sms * WPB);
}